// round 13
// baseline (speedup 1.0000x reference)
#include <cuda_runtime.h>
#include <math.h>
#include <stdint.h>

#define N_NODES 4096
#define FIN 20
#define H 4
#define D 64
#define TILE_C 64
#define ROWS_PER_BLK 32
#define NTILES (N_NODES / TILE_C)

// ---- k_attn smem layout (bytes) ----
// Wh tile per buffer: [4 h][64 j][64 c] f32 = 65536 (rows stored XOR-swizzled)
#define OFF_WH 0
#define WH_BYTES 65536
#define OFF_BITS (2 * WH_BYTES)          // 131072: [2 buf][32 rows][2 u32] = 512
#define OFF_FD (OFF_BITS + 512)          // 131584: [2 buf][4 h][64 j] f32 = 2048
#define OFF_L (OFF_FD + 2048)            // 133632: lbuf [4 h][4 jq][32] f32 = 2048
#define OFF_P (OFF_L + 2048)             // 135680: P [4 h][64 j][32 rows] u64 = 65536
#define ATTN_SMEM (OFF_P + 65536)        // 201216
#define WH1_SMEM ((64 * 256 + 256 * 64) * 4)   // 131072

// ---------------- device scratch ----------------
__device__ float g_Wh[H * N_NODES * D];   // [h][n][64] f32
__device__ float g_fs[H * N_NODES];
__device__ float g_fd[H * N_NODES];
__device__ float g_maxfd[H];
__device__ float g_h1[N_NODES * H * D];   // per-head elu outputs (both layers)
__device__ uint32_t g_bits[N_NODES * (N_NODES / 32)]; // adj bitmask [4096][128]

// ---------------- helpers ----------------
__device__ __forceinline__ float wsum(float v) {
#pragma unroll
    for (int s = 16; s > 0; s >>= 1) v += __shfl_xor_sync(0xffffffffu, v, s);
    return v;
}
__device__ __forceinline__ unsigned long long pack2(float x) {
    unsigned long long r;
    asm("mov.b64 %0, {%1, %1};" : "=l"(r) : "f"(x));
    return r;
}
__device__ __forceinline__ void fma2(unsigned long long& d, unsigned long long a,
                                     unsigned long long b) {
    asm("fma.rn.f32x2 %0, %1, %2, %0;" : "+l"(d) : "l"(a), "l"(b));
}
__device__ __forceinline__ float elu_f(float x) { return x > 0.f ? x : expm1f(x); }

__device__ __forceinline__ void cp16(uint32_t s, const void* g) {
    asm volatile("cp.async.cg.shared.global [%0], [%1], 16;" :: "r"(s), "l"(g));
}
__device__ __forceinline__ void cp8(uint32_t s, const void* g) {
    asm volatile("cp.async.ca.shared.global [%0], [%1], 8;" :: "r"(s), "l"(g));
}
__device__ __forceinline__ void cp_commit() { asm volatile("cp.async.commit_group;"); }
__device__ __forceinline__ void cp_wait0() { asm volatile("cp.async.wait_group 0;"); }
__device__ __forceinline__ uint32_t smem_u32(const void* p) {
    uint32_t a;
    asm("{ .reg .u64 t; cvta.to.shared.u64 t, %1; cvt.u32.u64 %0, t; }" : "=r"(a) : "l"(p));
    return a;
}

// ---------------- adj -> bitmask pack ----------------
__global__ void k_pack(const int* __restrict__ adj) {
    int row = blockIdx.x;
    int w = threadIdx.x >> 5, lane = threadIdx.x & 31;
    int grp = blockIdx.y * 8 + w;          // 16 * 8 = 128 groups
    int v = adj[(size_t)row * N_NODES + grp * 32 + lane];
    uint32_t mask = __ballot_sync(0xffffffffu, v != 0);
    if (lane == 0) g_bits[row * 128 + grp] = mask;
}

// ---------------- layer-0 projection ----------------
__global__ void k_wh0(const float* __restrict__ x, const float* __restrict__ W0,
                      const float* __restrict__ a0) {
    int h = blockIdx.y, o = threadIdx.x;
    int n0 = blockIdx.x * 8;
    __shared__ float xs[8][FIN];
    for (int idx = o; idx < 8 * FIN; idx += 64)
        xs[idx / FIN][idx % FIN] = x[n0 * FIN + idx];
    __syncthreads();
    float wh[8] = {0.f, 0.f, 0.f, 0.f, 0.f, 0.f, 0.f, 0.f};
#pragma unroll
    for (int f = 0; f < FIN; f++) {
        float w = W0[(h * FIN + f) * D + o];
#pragma unroll
        for (int r = 0; r < 8; r++) wh[r] += xs[r][f] * w;
    }
#pragma unroll
    for (int r = 0; r < 8; r++) g_Wh[(h * N_NODES + n0 + r) * D + o] = wh[r];

    float as = __ldg(a0 + h * 2 * D + o), ad = __ldg(a0 + h * 2 * D + D + o);
    __shared__ float rb[2][2][8];
    int w = o >> 5, lane = o & 31;
#pragma unroll
    for (int r = 0; r < 8; r++) {
        float ps = wsum(wh[r] * as);
        float pd = wsum(wh[r] * ad);
        if (lane == 0) { rb[0][w][r] = ps; rb[1][w][r] = pd; }
    }
    __syncthreads();
    if (o < 8) {
        g_fs[h * N_NODES + n0 + o] = rb[0][0][o] + rb[0][1][o];
        g_fd[h * N_NODES + n0 + o] = rb[1][0][o] + rb[1][1][o];
    }
}

// ---------------- layer-1 projection (smem-staged) ----------------
__global__ void __launch_bounds__(256)
k_wh1(const float* __restrict__ W1, const float* __restrict__ a1) {
    extern __shared__ float sm[];
    float* hs = sm;            // [64][256]
    float* ws = sm + 16384;    // [256][64]
    int h = blockIdx.y;
    int n0 = blockIdx.x * 64;
    int tid = threadIdx.x;
    int lane = tid & 31, rq = tid >> 5;

    const float4* hsrc = reinterpret_cast<const float4*>(g_h1 + (size_t)n0 * (H * D));
    const float4* wsrc = reinterpret_cast<const float4*>(W1 + (size_t)h * (H * D) * D);
    float4* hd = reinterpret_cast<float4*>(hs);
    float4* wd = reinterpret_cast<float4*>(ws);
#pragma unroll
    for (int v = tid; v < 4096; v += 256) { hd[v] = hsrc[v]; wd[v] = wsrc[v]; }
    __syncthreads();

    unsigned long long acc[8];
#pragma unroll
    for (int r = 0; r < 8; r++) acc[r] = 0ull;
    const float* hb = hs + (rq * 8) * (H * D);
#pragma unroll 4
    for (int f = 0; f < H * D; f++) {
        unsigned long long w2 =
            *reinterpret_cast<const unsigned long long*>(ws + f * D + 2 * lane);
#pragma unroll
        for (int r = 0; r < 8; r++) fma2(acc[r], pack2(hb[r * (H * D) + f]), w2);
    }
#pragma unroll
    for (int r = 0; r < 8; r++) {
        float2 t = *reinterpret_cast<float2*>(&acc[r]);
        *reinterpret_cast<float2*>(g_Wh + ((size_t)(h * N_NODES + n0 + rq * 8 + r)) * D +
                                   2 * lane) = t;
    }
    float2 as2 = *reinterpret_cast<const float2*>(a1 + h * 2 * D + 2 * lane);
    float2 ad2 = *reinterpret_cast<const float2*>(a1 + h * 2 * D + D + 2 * lane);
    __shared__ float rb[2][8][8];
#pragma unroll
    for (int r = 0; r < 8; r++) {
        float2 t = *reinterpret_cast<float2*>(&acc[r]);
        float ps = wsum(t.x * as2.x + t.y * as2.y);
        float pd = wsum(t.x * ad2.x + t.y * ad2.y);
        if (lane == 0) { rb[0][rq][r] = ps; rb[1][rq][r] = pd; }
    }
    __syncthreads();
    if (tid < 64) g_fs[h * N_NODES + n0 + tid] = rb[0][tid >> 3][tid & 7];
    else if (tid < 128) {
        int r = tid - 64;
        g_fd[h * N_NODES + n0 + r] = rb[1][r >> 3][r & 7];
    }
}

// ---------------- per-head max of fd ----------------
__global__ void k_maxfd() {
    int h = blockIdx.x;
    float mx = -1e30f;
    for (int j = threadIdx.x; j < N_NODES; j += 256)
        mx = fmaxf(mx, g_fd[h * N_NODES + j]);
#pragma unroll
    for (int s = 16; s > 0; s >>= 1) mx = fmaxf(mx, __shfl_xor_sync(0xffffffffu, mx, s));
    __shared__ float smx[8];
    if ((threadIdx.x & 31) == 0) smx[threadIdx.x >> 5] = mx;
    __syncthreads();
    if (threadIdx.x == 0) {
        float r = smx[0];
#pragma unroll
        for (int i = 1; i < 8; i++) r = fmaxf(r, smx[i]);
        g_maxfd[h] = r;
    }
}

// XOR-32B swizzle: chunk c (16B) of a 256B row stored at
// (c>>2)*64 + ((c&3)*16 ^ ((c&8)?32:0)). For any load index i, the 4 cg
// groups then occupy banks {0-7},{8-15},{16-23},{24-31} -> conflict-free.
__device__ __forceinline__ uint32_t wh_swz(int c) {
    return (uint32_t)(((c >> 2) * 64) + (((c & 3) * 16) ^ ((c & 8) ? 32 : 0)));
}

// ---------------- tile stage (512 threads) ----------------
__device__ __forceinline__ void stage_tile(uint32_t sb, int buf, int rowbase, int jb,
                                           int tid) {
    int jbase = jb * TILE_C;
    uint32_t wh = sb + OFF_WH + buf * WH_BYTES;
#pragma unroll
    for (int v = tid; v < 4096; v += 512) {
        int hh = v >> 10, j = (v >> 4) & 63, c = v & 15;
        cp16(wh + (uint32_t)(hh * 64 + j) * 256u + wh_swz(c),
             g_Wh + ((size_t)(hh * N_NODES + jbase + j)) * D + c * 4);
    }
    if (tid < 32)
        cp8(sb + OFF_BITS + buf * 256 + tid * 8,
            g_bits + (size_t)(rowbase + tid) * 128 + jb * 2);
    else if (tid < 96) {
        int t = tid - 32;   // 64 chunks: h = t>>4, 4 floats each
        cp16(sb + OFF_FD + buf * 1024 + t * 16,
             g_fd + (t >> 4) * N_NODES + jbase + (t & 15) * 4);
    }
    cp_commit();
}

// ---------------- fused GAT attention: register-tiled FFMA2, pre-packed P ----------------
// grid 128, block 512 = 16 warps: warp = (h = w&3, jq = w>>2).
// P-stage: lane=row computes 16 masked-exp scores, stores PACKED {p,p} u64 into
// smem panel. GEMM: lane (rg,cg) = 4 rows x 16 cols; per j: 2 LDS.128 of packed p
// + 4 conflict-free LDS.128 of Wh + 32 FFMA2, zero pack2 in the hot loop.
__global__ void __launch_bounds__(512)
k_attn(float* __restrict__ outbuf) {
    extern __shared__ char smc[];
    uint32_t sb = smem_u32(smc);
    int tid = threadIdx.x;
    int ln = tid & 31;
    int w = tid >> 5;
    int h = w & 3;
    int jq = w >> 2;
    int rg = ln >> 2, cg = ln & 3;
    int rowbase = blockIdx.x * ROWS_PER_BLK;

    // p-compute state for row = ln
    float fs = g_fs[h * N_NODES + rowbase + ln];
    float m = fs + g_maxfd[h];
    m = fmaxf(m, 0.2f * m);
    float l = 0.f;

    unsigned long long acc[32];
#pragma unroll
    for (int c = 0; c < 32; c++) acc[c] = 0ull;

    stage_tile(sb, 0, rowbase, 0, tid);
    cp_wait0();
    __syncthreads();

    int sh0 = (jq & 1) * 16;
    int wword = jq >> 1;
    uint32_t swz = (uint32_t)((cg & 2) << 4);   // 0 or 32
    unsigned long long* Pp =
        (unsigned long long*)(smc + OFF_P) + (h * 64 + jq * 16) * 32;  // warp panel
    const unsigned long long* Pg =
        (const unsigned long long*)(smc + OFF_P) + (h * 64 + jq * 16) * 32 + rg * 4;

    for (int jb = 0; jb < NTILES; jb++) {
        int buf = jb & 1;
        if (jb + 1 < NTILES) stage_tile(sb, buf ^ 1, rowbase, jb + 1, tid);

        const char* whs = smc + OFF_WH + buf * WH_BYTES;
        const uint32_t* bitsb = (const uint32_t*)(smc + OFF_BITS + buf * 256);
        const float* fdsb = (const float*)(smc + OFF_FD + buf * 1024);
        uint32_t bw = bitsb[ln * 2 + wword];

        // ---- P-stage: 16 masked-exp scores for row = ln, stored packed ----
#pragma unroll
        for (int jj = 0; jj < 16; jj++) {
            float e = fs + fdsb[h * 64 + jq * 16 + jj];
            e = fmaxf(e, 0.2f * e);                 // LeakyReLU(0.2)
            float ex = __expf(e - m);
            float p = ((bw >> (sh0 + jj)) & 1u) ? ex : 0.f;
            l += p;
            Pp[jj * 32 + ln] = pack2(p);
        }
        __syncwarp();

        // ---- GEMM: 32 rows x 64 cols for (h, jq), thread tile 4x16 ----
        const char* whrow = whs + (h * 64 + jq * 16) * 256 + cg * 64;
#pragma unroll 8
        for (int jj = 0; jj < 16; jj++) {
            ulonglong2 q01 = *reinterpret_cast<const ulonglong2*>(Pg + jj * 32);
            ulonglong2 q23 = *reinterpret_cast<const ulonglong2*>(Pg + jj * 32 + 2);
            const char* wr = whrow + jj * 256;
            ulonglong2 wa = *reinterpret_cast<const ulonglong2*>(wr + (0u ^ swz));
            ulonglong2 wb = *reinterpret_cast<const ulonglong2*>(wr + (16u ^ swz));
            ulonglong2 wc = *reinterpret_cast<const ulonglong2*>(wr + (32u ^ swz));
            ulonglong2 wd = *reinterpret_cast<const ulonglong2*>(wr + (48u ^ swz));
            fma2(acc[0], wa.x, q01.x); fma2(acc[1], wa.y, q01.x);
            fma2(acc[2], wb.x, q01.x); fma2(acc[3], wb.y, q01.x);
            fma2(acc[4], wc.x, q01.x); fma2(acc[5], wc.y, q01.x);
            fma2(acc[6], wd.x, q01.x); fma2(acc[7], wd.y, q01.x);
            fma2(acc[8], wa.x, q01.y); fma2(acc[9], wa.y, q01.y);
            fma2(acc[10], wb.x, q01.y); fma2(acc[11], wb.y, q01.y);
            fma2(acc[12], wc.x, q01.y); fma2(acc[13], wc.y, q01.y);
            fma2(acc[14], wd.x, q01.y); fma2(acc[15], wd.y, q01.y);
            fma2(acc[16], wa.x, q23.x); fma2(acc[17], wa.y, q23.x);
            fma2(acc[18], wb.x, q23.x); fma2(acc[19], wb.y, q23.x);
            fma2(acc[20], wc.x, q23.x); fma2(acc[21], wc.y, q23.x);
            fma2(acc[22], wd.x, q23.x); fma2(acc[23], wd.y, q23.x);
            fma2(acc[24], wa.x, q23.y); fma2(acc[25], wa.y, q23.y);
            fma2(acc[26], wb.x, q23.y); fma2(acc[27], wb.y, q23.y);
            fma2(acc[28], wc.x, q23.y); fma2(acc[29], wc.y, q23.y);
            fma2(acc[30], wd.x, q23.y); fma2(acc[31], wd.y, q23.y);
        }
        cp_wait0();
        __syncthreads();
    }

    // ---- epilogue: combine 4 j-quarter partials ----
    float* lbuf = (float*)(smc + OFF_L);          // [h][jq][32]
    float* part = (float*)smc;                     // reuse Wh buffers: [3][h][32][64]
    lbuf[(h * 4 + jq) * 32 + ln] = l;
    if (jq > 0) {
#pragma unroll
        for (int r = 0; r < 4; r++) {
            int row = rg * 4 + r;
            float2* dst = (float2*)(part + ((jq - 1) * 128 + h * 32 + row) * 64 + cg * 16);
#pragma unroll
            for (int c = 0; c < 8; c++) dst[c] = *reinterpret_cast<float2*>(&acc[r * 8 + c]);
        }
    }
    __syncthreads();

    if (jq == 0) {
#pragma unroll
        for (int r = 0; r < 4; r++) {
            int row = rg * 4 + r;
            float lsum = lbuf[h * 128 + row] + lbuf[h * 128 + 32 + row] +
                         lbuf[h * 128 + 64 + row] + lbuf[h * 128 + 96 + row];
            float inv = 1.0f / fmaxf(lsum, 1e-30f);
            const float2* q0 = (const float2*)(part + (0 * 128 + h * 32 + row) * 64 + cg * 16);
            const float2* q1 = (const float2*)(part + (1 * 128 + h * 32 + row) * 64 + cg * 16);
            const float2* q2 = (const float2*)(part + (2 * 128 + h * 32 + row) * 64 + cg * 16);
            float2* dst = (float2*)(outbuf + (size_t)(rowbase + row) * (H * D) + h * D +
                                    cg * 16);
#pragma unroll
            for (int c = 0; c < 8; c++) {
                float2 a = *reinterpret_cast<float2*>(&acc[r * 8 + c]);
                float2 b0 = q0[c], b1 = q1[c], b2 = q2[c];
                float2 v;
                v.x = elu_f((a.x + b0.x + b1.x + b2.x) * inv);
                v.y = elu_f((a.y + b0.y + b1.y + b2.y) * inv);
                dst[c] = v;
            }
        }
    }
}

// ---------------- head average (final epilogue) ----------------
__global__ void k_avg(float* __restrict__ out) {
    int idx = blockIdx.x * 256 + threadIdx.x;     // 65536 float4s
    int n = idx >> 4, v = idx & 15;
    const float4* src = reinterpret_cast<const float4*>(g_h1 + (size_t)n * (H * D));
    float4 a = src[v], b = src[16 + v], c = src[32 + v], d = src[48 + v];
    float4 r;
    r.x = 0.25f * (a.x + b.x + c.x + d.x);
    r.y = 0.25f * (a.y + b.y + c.y + d.y);
    r.z = 0.25f * (a.z + b.z + c.z + d.z);
    r.w = 0.25f * (a.w + b.w + c.w + d.w);
    reinterpret_cast<float4*>(out)[idx] = r;
}

// ---------------- launch ----------------
extern "C" void kernel_launch(void* const* d_in, const int* in_sizes, int n_in,
                              void* d_out, int out_size) {
    const float* x = (const float*)d_in[0];
    const int* adj = (const int*)d_in[1];
    const float* W0 = (const float*)d_in[2];
    const float* a0 = (const float*)d_in[3];
    const float* W1 = (const float*)d_in[4];
    const float* a1 = (const float*)d_in[5];
    float* out = (float*)d_out;

    cudaFuncSetAttribute(k_attn, cudaFuncAttributeMaxDynamicSharedMemorySize, ATTN_SMEM);
    cudaFuncSetAttribute(k_wh1, cudaFuncAttributeMaxDynamicSharedMemorySize, WH1_SMEM);

    float* g_h1_ptr = nullptr;
    cudaGetSymbolAddress((void**)&g_h1_ptr, g_h1);

    k_pack<<<dim3(N_NODES, 16), 256>>>(adj);

    // layer 0
    k_wh0<<<dim3(N_NODES / 8, H), 64>>>(x, W0, a0);
    k_maxfd<<<H, 256>>>();
    k_attn<<<N_NODES / ROWS_PER_BLK, 512, ATTN_SMEM>>>(g_h1_ptr);

    // layer 1
    k_wh1<<<dim3(N_NODES / 64, H), 256, WH1_SMEM>>>(W1, a1);
    k_maxfd<<<H, 256>>>();
    k_attn<<<N_NODES / ROWS_PER_BLK, 512, ATTN_SMEM>>>(g_h1_ptr);
    k_avg<<<256, 256>>>(out);
}

// round 15
// speedup vs baseline: 1.1312x; 1.1312x over previous
#include <cuda_runtime.h>
#include <math.h>
#include <stdint.h>

#define N_NODES 4096
#define FIN 20
#define H 4
#define HPC 2                 // heads per CTA
#define D 64
#define TILE_C 64
#define ROWS_PER_BLK 32
#define NTILES (N_NODES / TILE_C)

// ---- k_attn smem layout (bytes), per CTA ----
// Wh tile per buffer: [2 h][64 j][64 c] f32 = 32768 (rows XOR-swizzled)
#define OFF_WH 0
#define WH_BYTES 32768
#define OFF_BITS (2 * WH_BYTES)          // 65536: [2 buf][32 rows][2 u32] = 512
#define OFF_FD (OFF_BITS + 512)          // 66048: [2 buf][2 h][64 j] f32 = 1024
#define OFF_L (OFF_FD + 1024)            // 67072: lbuf [2 h][4 jq][32] f32 = 1024
#define OFF_P (OFF_L + 1024)             // 68096: P [2 h][64 j][32 rows] f32 = 16384
#define ATTN_SMEM (OFF_P + 16384)        // 84480  (x2 CTAs = 168960 < 228K)
#define WH1_SMEM ((64 * 256 + 256 * 64) * 4)   // 131072

// ---------------- device scratch ----------------
__device__ float g_Wh[H * N_NODES * D];   // [h][n][64] f32
__device__ float g_fs[H * N_NODES];
__device__ float g_fd[H * N_NODES];
__device__ float g_maxfd[H];
__device__ float g_h1[N_NODES * H * D];   // per-head elu outputs (both layers)
__device__ uint32_t g_bits[N_NODES * (N_NODES / 32)]; // adj bitmask [4096][128]

// ---------------- helpers ----------------
__device__ __forceinline__ float wsum(float v) {
#pragma unroll
    for (int s = 16; s > 0; s >>= 1) v += __shfl_xor_sync(0xffffffffu, v, s);
    return v;
}
__device__ __forceinline__ unsigned long long pack2(float x) {
    unsigned long long r;
    asm("mov.b64 %0, {%1, %1};" : "=l"(r) : "f"(x));
    return r;
}
__device__ __forceinline__ void fma2(unsigned long long& d, unsigned long long a,
                                     unsigned long long b) {
    asm("fma.rn.f32x2 %0, %1, %2, %0;" : "+l"(d) : "l"(a), "l"(b));
}
__device__ __forceinline__ float elu_f(float x) { return x > 0.f ? x : expm1f(x); }

__device__ __forceinline__ void cp16(uint32_t s, const void* g) {
    asm volatile("cp.async.cg.shared.global [%0], [%1], 16;" :: "r"(s), "l"(g));
}
__device__ __forceinline__ void cp8(uint32_t s, const void* g) {
    asm volatile("cp.async.ca.shared.global [%0], [%1], 8;" :: "r"(s), "l"(g));
}
__device__ __forceinline__ void cp_commit() { asm volatile("cp.async.commit_group;"); }
__device__ __forceinline__ void cp_wait0() { asm volatile("cp.async.wait_group 0;"); }
__device__ __forceinline__ uint32_t smem_u32(const void* p) {
    uint32_t a;
    asm("{ .reg .u64 t; cvta.to.shared.u64 t, %1; cvt.u32.u64 %0, t; }" : "=r"(a) : "l"(p));
    return a;
}

// ---------------- adj -> bitmask pack ----------------
__global__ void k_pack(const int* __restrict__ adj) {
    int row = blockIdx.x;
    int w = threadIdx.x >> 5, lane = threadIdx.x & 31;
    int grp = blockIdx.y * 8 + w;          // 16 * 8 = 128 groups
    int v = adj[(size_t)row * N_NODES + grp * 32 + lane];
    uint32_t mask = __ballot_sync(0xffffffffu, v != 0);
    if (lane == 0) g_bits[row * 128 + grp] = mask;
}

// ---------------- layer-0 projection ----------------
__global__ void k_wh0(const float* __restrict__ x, const float* __restrict__ W0,
                      const float* __restrict__ a0) {
    int h = blockIdx.y, o = threadIdx.x;
    int n0 = blockIdx.x * 8;
    __shared__ float xs[8][FIN];
    for (int idx = o; idx < 8 * FIN; idx += 64)
        xs[idx / FIN][idx % FIN] = x[n0 * FIN + idx];
    __syncthreads();
    float wh[8] = {0.f, 0.f, 0.f, 0.f, 0.f, 0.f, 0.f, 0.f};
#pragma unroll
    for (int f = 0; f < FIN; f++) {
        float w = W0[(h * FIN + f) * D + o];
#pragma unroll
        for (int r = 0; r < 8; r++) wh[r] += xs[r][f] * w;
    }
#pragma unroll
    for (int r = 0; r < 8; r++) g_Wh[(h * N_NODES + n0 + r) * D + o] = wh[r];

    float as = __ldg(a0 + h * 2 * D + o), ad = __ldg(a0 + h * 2 * D + D + o);
    __shared__ float rb[2][2][8];
    int w = o >> 5, lane = o & 31;
#pragma unroll
    for (int r = 0; r < 8; r++) {
        float ps = wsum(wh[r] * as);
        float pd = wsum(wh[r] * ad);
        if (lane == 0) { rb[0][w][r] = ps; rb[1][w][r] = pd; }
    }
    __syncthreads();
    if (o < 8) {
        g_fs[h * N_NODES + n0 + o] = rb[0][0][o] + rb[0][1][o];
        g_fd[h * N_NODES + n0 + o] = rb[1][0][o] + rb[1][1][o];
    }
}

// ---------------- layer-1 projection (smem-staged) ----------------
__global__ void __launch_bounds__(256)
k_wh1(const float* __restrict__ W1, const float* __restrict__ a1) {
    extern __shared__ float sm[];
    float* hs = sm;            // [64][256]
    float* ws = sm + 16384;    // [256][64]
    int h = blockIdx.y;
    int n0 = blockIdx.x * 64;
    int tid = threadIdx.x;
    int lane = tid & 31, rq = tid >> 5;

    const float4* hsrc = reinterpret_cast<const float4*>(g_h1 + (size_t)n0 * (H * D));
    const float4* wsrc = reinterpret_cast<const float4*>(W1 + (size_t)h * (H * D) * D);
    float4* hd = reinterpret_cast<float4*>(hs);
    float4* wd = reinterpret_cast<float4*>(ws);
#pragma unroll
    for (int v = tid; v < 4096; v += 256) { hd[v] = hsrc[v]; wd[v] = wsrc[v]; }
    __syncthreads();

    unsigned long long acc[8];
#pragma unroll
    for (int r = 0; r < 8; r++) acc[r] = 0ull;
    const float* hb = hs + (rq * 8) * (H * D);
#pragma unroll 4
    for (int f = 0; f < H * D; f++) {
        unsigned long long w2 =
            *reinterpret_cast<const unsigned long long*>(ws + f * D + 2 * lane);
#pragma unroll
        for (int r = 0; r < 8; r++) fma2(acc[r], pack2(hb[r * (H * D) + f]), w2);
    }
#pragma unroll
    for (int r = 0; r < 8; r++) {
        float2 t = *reinterpret_cast<float2*>(&acc[r]);
        *reinterpret_cast<float2*>(g_Wh + ((size_t)(h * N_NODES + n0 + rq * 8 + r)) * D +
                                   2 * lane) = t;
    }
    float2 as2 = *reinterpret_cast<const float2*>(a1 + h * 2 * D + 2 * lane);
    float2 ad2 = *reinterpret_cast<const float2*>(a1 + h * 2 * D + D + 2 * lane);
    __shared__ float rb[2][8][8];
#pragma unroll
    for (int r = 0; r < 8; r++) {
        float2 t = *reinterpret_cast<float2*>(&acc[r]);
        float ps = wsum(t.x * as2.x + t.y * as2.y);
        float pd = wsum(t.x * ad2.x + t.y * ad2.y);
        if (lane == 0) { rb[0][rq][r] = ps; rb[1][rq][r] = pd; }
    }
    __syncthreads();
    if (tid < 64) g_fs[h * N_NODES + n0 + tid] = rb[0][tid >> 3][tid & 7];
    else if (tid < 128) {
        int r = tid - 64;
        g_fd[h * N_NODES + n0 + r] = rb[1][r >> 3][r & 7];
    }
}

// ---------------- per-head max of fd ----------------
__global__ void k_maxfd() {
    int h = blockIdx.x;
    float mx = -1e30f;
    for (int j = threadIdx.x; j < N_NODES; j += 256)
        mx = fmaxf(mx, g_fd[h * N_NODES + j]);
#pragma unroll
    for (int s = 16; s > 0; s >>= 1) mx = fmaxf(mx, __shfl_xor_sync(0xffffffffu, mx, s));
    __shared__ float smx[8];
    if ((threadIdx.x & 31) == 0) smx[threadIdx.x >> 5] = mx;
    __syncthreads();
    if (threadIdx.x == 0) {
        float r = smx[0];
#pragma unroll
        for (int i = 1; i < 8; i++) r = fmaxf(r, smx[i]);
        g_maxfd[h] = r;
    }
}

// XOR-32B swizzle: chunk c (16B) of a 256B row stored at
// (c>>2)*64 + ((c&3)*16 ^ ((c&8)?32:0)) -> 4 cg groups hit disjoint bank quads.
__device__ __forceinline__ uint32_t wh_swz(int c) {
    return (uint32_t)(((c >> 2) * 64) + (((c & 3) * 16) ^ ((c & 8) ? 32 : 0)));
}

// ---------------- tile stage (256 threads, 2 heads) ----------------
__device__ __forceinline__ void stage_tile(uint32_t sb, int buf, int hbase, int rowbase,
                                           int jb, int tid) {
    int jbase = jb * TILE_C;
    uint32_t wh = sb + OFF_WH + buf * WH_BYTES;
#pragma unroll
    for (int v = tid; v < 2048; v += 256) {
        int hh = v >> 10, j = (v >> 4) & 63, c = v & 15;
        cp16(wh + (uint32_t)(hh * 64 + j) * 256u + wh_swz(c),
             g_Wh + ((size_t)((hbase + hh) * N_NODES + jbase + j)) * D + c * 4);
    }
    if (tid < 32)
        cp8(sb + OFF_BITS + buf * 256 + tid * 8,
            g_bits + (size_t)(rowbase + tid) * 128 + jb * 2);
    else if (tid < 64) {
        int t = tid - 32;   // 32 chunks: hh = t>>4, 4 floats each
        cp16(sb + OFF_FD + buf * 512 + t * 16,
             g_fd + (hbase + (t >> 4)) * N_NODES + jbase + (t & 15) * 4);
    }
    cp_commit();
}

// ---------------- fused GAT attention: 2 CTAs/SM, R12 inner loop ----------------
// grid (128 rowblocks, H/2), block 256 = 8 warps: warp = (h_local = w&1, jq = w>>1).
// Per tile: P-stage (lane=row, 16 masked-exp scores -> f32 smem panel), syncwarp,
// GEMM lane (rg,cg) = 4 rows x 16 cols: 1 LDS.128 p + 4 swizzled LDS.128 Wh + 32 FFMA2.
__global__ void __launch_bounds__(256, 2)
k_attn(float* __restrict__ outbuf) {
    extern __shared__ char smc[];
    uint32_t sb = smem_u32(smc);
    int tid = threadIdx.x;
    int ln = tid & 31;
    int w = tid >> 5;
    int hl = w & 1;                       // local head 0..1
    int jq = w >> 1;                      // 0..3
    int h = blockIdx.y * HPC + hl;
    int hbase = blockIdx.y * HPC;
    int rg = ln >> 2, cg = ln & 3;
    int rowbase = blockIdx.x * ROWS_PER_BLK;

    // p-compute state for row = ln
    float fs = g_fs[h * N_NODES + rowbase + ln];
    float m = fs + g_maxfd[h];
    m = fmaxf(m, 0.2f * m);
    float l = 0.f;

    unsigned long long acc[32];
#pragma unroll
    for (int c = 0; c < 32; c++) acc[c] = 0ull;

    stage_tile(sb, 0, hbase, rowbase, 0, tid);
    cp_wait0();
    __syncthreads();

    int sh0 = (jq & 1) * 16;
    int wword = jq >> 1;
    uint32_t swz = (uint32_t)((cg & 2) << 4);   // 0 or 32
    float* Pp = (float*)(smc + OFF_P) + (hl * 64 + jq * 16) * 32;   // warp panel
    const float* Pg = (const float*)(smc + OFF_P) + (hl * 64 + jq * 16) * 32 + rg * 4;

    for (int jb = 0; jb < NTILES; jb++) {
        int buf = jb & 1;
        if (jb + 1 < NTILES) stage_tile(sb, buf ^ 1, hbase, rowbase, jb + 1, tid);

        const char* whs = smc + OFF_WH + buf * WH_BYTES;
        const uint32_t* bitsb = (const uint32_t*)(smc + OFF_BITS + buf * 256);
        const float* fdsb = (const float*)(smc + OFF_FD + buf * 512);
        uint32_t bw = bitsb[ln * 2 + wword];

        // ---- P-stage: 16 masked-exp scores for row = ln ----
#pragma unroll
        for (int jj = 0; jj < 16; jj++) {
            float e = fs + fdsb[hl * 64 + jq * 16 + jj];
            e = fmaxf(e, 0.2f * e);                 // LeakyReLU(0.2)
            float ex = __expf(e - m);
            float p = ((bw >> (sh0 + jj)) & 1u) ? ex : 0.f;
            l += p;
            Pp[jj * 32 + ln] = p;
        }
        __syncwarp();

        // ---- GEMM: 32 rows x 64 cols for (hl, jq), thread tile 4x16 ----
        const char* whrow = whs + (hl * 64 + jq * 16) * 256 + cg * 64;
#pragma unroll 8
        for (int jj = 0; jj < 16; jj++) {
            float4 pv = *reinterpret_cast<const float4*>(Pg + jj * 32);
            const char* wr = whrow + jj * 256;
            ulonglong2 wa = *reinterpret_cast<const ulonglong2*>(wr + (0u ^ swz));
            ulonglong2 wb = *reinterpret_cast<const ulonglong2*>(wr + (16u ^ swz));
            ulonglong2 wc = *reinterpret_cast<const ulonglong2*>(wr + (32u ^ swz));
            ulonglong2 wd = *reinterpret_cast<const ulonglong2*>(wr + (48u ^ swz));
            unsigned long long q;
            q = pack2(pv.x);
            fma2(acc[0], wa.x, q); fma2(acc[1], wa.y, q); fma2(acc[2], wb.x, q);
            fma2(acc[3], wb.y, q); fma2(acc[4], wc.x, q); fma2(acc[5], wc.y, q);
            fma2(acc[6], wd.x, q); fma2(acc[7], wd.y, q);
            q = pack2(pv.y);
            fma2(acc[8], wa.x, q); fma2(acc[9], wa.y, q); fma2(acc[10], wb.x, q);
            fma2(acc[11], wb.y, q); fma2(acc[12], wc.x, q); fma2(acc[13], wc.y, q);
            fma2(acc[14], wd.x, q); fma2(acc[15], wd.y, q);
            q = pack2(pv.z);
            fma2(acc[16], wa.x, q); fma2(acc[17], wa.y, q); fma2(acc[18], wb.x, q);
            fma2(acc[19], wb.y, q); fma2(acc[20], wc.x, q); fma2(acc[21], wc.y, q);
            fma2(acc[22], wd.x, q); fma2(acc[23], wd.y, q);
            q = pack2(pv.w);
            fma2(acc[24], wa.x, q); fma2(acc[25], wa.y, q); fma2(acc[26], wb.x, q);
            fma2(acc[27], wb.y, q); fma2(acc[28], wc.x, q); fma2(acc[29], wc.y, q);
            fma2(acc[30], wd.x, q); fma2(acc[31], wd.y, q);
        }
        cp_wait0();
        __syncthreads();
    }

    // ---- epilogue: combine 4 j-quarter partials per (head,row) ----
    float* lbuf = (float*)(smc + OFF_L);          // [hl][jq][32]
    float* part = (float*)smc;                     // reuse Wh buffers: [3][2 h][32][64]
    lbuf[(hl * 4 + jq) * 32 + ln] = l;
    if (jq > 0) {
#pragma unroll
        for (int r = 0; r < 4; r++) {
            int row = rg * 4 + r;
            float2* dst = (float2*)(part + (((jq - 1) * HPC + hl) * 32 + row) * 64 + cg * 16);
#pragma unroll
            for (int c = 0; c < 8; c++) dst[c] = *reinterpret_cast<float2*>(&acc[r * 8 + c]);
        }
    }
    __syncthreads();

    if (jq == 0) {
#pragma unroll
        for (int r = 0; r < 4; r++) {
            int row = rg * 4 + r;
            float lsum = lbuf[hl * 128 + row] + lbuf[hl * 128 + 32 + row] +
                         lbuf[hl * 128 + 64 + row] + lbuf[hl * 128 + 96 + row];
            float inv = 1.0f / fmaxf(lsum, 1e-30f);
            const float2* q0 = (const float2*)(part + ((0 * HPC + hl) * 32 + row) * 64 + cg * 16);
            const float2* q1 = (const float2*)(part + ((1 * HPC + hl) * 32 + row) * 64 + cg * 16);
            const float2* q2 = (const float2*)(part + ((2 * HPC + hl) * 32 + row) * 64 + cg * 16);
            float2* dst = (float2*)(outbuf + (size_t)(rowbase + row) * (H * D) + h * D +
                                    cg * 16);
#pragma unroll
            for (int c = 0; c < 8; c++) {
                float2 a = *reinterpret_cast<float2*>(&acc[r * 8 + c]);
                float2 b0 = q0[c], b1 = q1[c], b2 = q2[c];
                float2 v;
                v.x = elu_f((a.x + b0.x + b1.x + b2.x) * inv);
                v.y = elu_f((a.y + b0.y + b1.y + b2.y) * inv);
                dst[c] = v;
            }
        }
    }
}

// ---------------- head average (final epilogue) ----------------
__global__ void k_avg(float* __restrict__ out) {
    int idx = blockIdx.x * 256 + threadIdx.x;     // 65536 float4s
    int n = idx >> 4, v = idx & 15;
    const float4* src = reinterpret_cast<const float4*>(g_h1 + (size_t)n * (H * D));
    float4 a = src[v], b = src[16 + v], c = src[32 + v], d = src[48 + v];
    float4 r;
    r.x = 0.25f * (a.x + b.x + c.x + d.x);
    r.y = 0.25f * (a.y + b.y + c.y + d.y);
    r.z = 0.25f * (a.z + b.z + c.z + d.z);
    r.w = 0.25f * (a.w + b.w + c.w + d.w);
    reinterpret_cast<float4*>(out)[idx] = r;
}

// ---------------- launch ----------------
extern "C" void kernel_launch(void* const* d_in, const int* in_sizes, int n_in,
                              void* d_out, int out_size) {
    const float* x = (const float*)d_in[0];
    const int* adj = (const int*)d_in[1];
    const float* W0 = (const float*)d_in[2];
    const float* a0 = (const float*)d_in[3];
    const float* W1 = (const float*)d_in[4];
    const float* a1 = (const float*)d_in[5];
    float* out = (float*)d_out;

    cudaFuncSetAttribute(k_attn, cudaFuncAttributeMaxDynamicSharedMemorySize, ATTN_SMEM);
    cudaFuncSetAttribute(k_wh1, cudaFuncAttributeMaxDynamicSharedMemorySize, WH1_SMEM);

    float* g_h1_ptr = nullptr;
    cudaGetSymbolAddress((void**)&g_h1_ptr, g_h1);

    k_pack<<<dim3(N_NODES, 16), 256>>>(adj);

    // layer 0
    k_wh0<<<dim3(N_NODES / 8, H), 64>>>(x, W0, a0);
    k_maxfd<<<H, 256>>>();
    k_attn<<<dim3(N_NODES / ROWS_PER_BLK, H / HPC), 256, ATTN_SMEM>>>(g_h1_ptr);

    // layer 1
    k_wh1<<<dim3(N_NODES / 64, H), 256, WH1_SMEM>>>(W1, a1);
    k_maxfd<<<H, 256>>>();
    k_attn<<<dim3(N_NODES / ROWS_PER_BLK, H / HPC), 256, ATTN_SMEM>>>(g_h1_ptr);
    k_avg<<<256, 256>>>(out);
}